// round 12
// baseline (speedup 1.0000x reference)
#include <cuda_runtime.h>
#include <cstdint>

// 2D acoustic FDTD, 4 shots x 512 steps, 256x256 grid.
// One cluster per shot, CSZ CTAs x 1024 threads. 128 column-PAIR threads x
// NG row groups; packed f32x2 math (FFMA2). p_t / -p_{t-1} pairs in
// registers; HORIZONTAL neighbors via warp shuffles (register exchange),
// smem mirror only for seams + halos + warp-edge fixups + receivers.
// Halo rows pushed with st.async.b64 + parity mbarriers, BOUNDARY-FIRST.
// Single full-CTA barrier per step; time loop unrolled x4 with literal
// mbar parities.

#define NS    4
#define NT    512
#define NZ    256
#define NX    256
#define NR    128
#define S     260          // padded row stride: cols [2..257] live, pads 0
#define NG    8            // row groups (1024 threads / 128 col-pairs)

typedef unsigned long long u64;

__device__ __forceinline__ uint32_t smem_u32(const void* p) {
    uint32_t a;
    asm("{ .reg .u64 t; cvta.to.shared.u64 t, %1; cvt.u32.u64 %0, t; }"
        : "=r"(a) : "l"(p));
    return a;
}
__device__ __forceinline__ uint32_t mapa32(uint32_t laddr, uint32_t rank) {
    uint32_t ra;
    asm("mapa.shared::cluster.u32 %0, %1, %2;" : "=r"(ra) : "r"(laddr), "r"(rank));
    return ra;
}
__device__ __forceinline__ void mbar_init(uint32_t mbar, uint32_t cnt) {
    asm volatile("mbarrier.init.shared::cta.b64 [%0], %1;" :: "r"(mbar), "r"(cnt) : "memory");
}
__device__ __forceinline__ void mbar_expect(uint32_t mbar, uint32_t tx) {
    asm volatile("mbarrier.arrive.expect_tx.shared::cta.b64 _, [%0], %1;"
                 :: "r"(mbar), "r"(tx) : "memory");
}
__device__ __forceinline__ void mbar_wait(uint32_t mbar, uint32_t parity) {
    asm volatile(
        "{\n\t"
        ".reg .pred P;\n\t"
        "LW%=:\n\t"
        "mbarrier.try_wait.parity.acquire.cluster.shared::cta.b64 P, [%0], %1;\n\t"
        "@P bra LD%=;\n\t"
        "bra LW%=;\n\t"
        "LD%=:\n\t"
        "}"
        :: "r"(mbar), "r"(parity) : "memory");
}
__device__ __forceinline__ void st_async_f2(uint32_t rslot, uint32_t rmbar, u64 v) {
    asm volatile("st.async.shared::cluster.mbarrier::complete_tx::bytes.b64 [%0], %1, [%2];"
                 :: "r"(rslot), "l"(v), "r"(rmbar) : "memory");
}
__device__ __forceinline__ void cluster_sync_() {
    asm volatile("barrier.cluster.arrive.aligned;" ::: "memory");
    asm volatile("barrier.cluster.wait.aligned;" ::: "memory");
}

// ---- packed f32x2 helpers ----
__device__ __forceinline__ u64 f2pack(float lo, float hi) {
    u64 r; asm("mov.b64 %0, {%1, %2};" : "=l"(r) : "f"(lo), "f"(hi)); return r;
}
__device__ __forceinline__ void f2unpack(u64 v, float& lo, float& hi) {
    asm("mov.b64 {%0, %1}, %2;" : "=f"(lo), "=f"(hi) : "l"(v));
}
__device__ __forceinline__ u64 f2add(u64 a, u64 b) {
    u64 r; asm("add.rn.f32x2 %0, %1, %2;" : "=l"(r) : "l"(a), "l"(b)); return r;
}
__device__ __forceinline__ u64 f2mul(u64 a, u64 b) {
    u64 r; asm("mul.rn.f32x2 %0, %1, %2;" : "=l"(r) : "l"(a), "l"(b)); return r;
}
__device__ __forceinline__ u64 f2fma(u64 a, u64 b, u64 c) {
    u64 r; asm("fma.rn.f32x2 %0, %1, %2, %3;" : "=l"(r) : "l"(a), "l"(b), "l"(c)); return r;
}
__device__ __forceinline__ u64 f2ld(const float* p) {        // aligned LDS.64
    float2 v = *(const float2*)p; return f2pack(v.x, v.y);
}
__device__ __forceinline__ void f2st(float* p, u64 v) {      // aligned STS.64
    float lo, hi; f2unpack(v, lo, hi);
    *(float2*)p = make_float2(lo, hi);
}

template<int CSZ>
__global__ void __launch_bounds__(1024, 1) __cluster_dims__(CSZ, 1, 1)
wave_kernel(const float* __restrict__ xin,   // (NS, NT)
            const float* __restrict__ vp,    // (NZ, NX)
            const int*   __restrict__ src_z, // (NS,)
            const int*   __restrict__ src_x, // (NS,)
            const int*   __restrict__ rec_z, // (NS, NR)
            const int*   __restrict__ rec_x, // (NS, NR)
            float*       __restrict__ out)   // (NS, NT, NR, 1)
{
    constexpr int RPC  = NZ / CSZ;      // rows per CTA
    constexpr int RPT  = RPC / NG;      // rows per thread
    constexpr int ROWS = RPC + 2;       // + halo rows 0 and ROWS-1
    extern __shared__ float smem[];     // [2][ROWS][S]
    __shared__ __align__(8) uint64_t mbars[4];  // [0/1]=top par, [2/3]=bot par
    __shared__ float sxin[NT];          // precomputed wav_t * DT * DT
    __shared__ int   rcnt;
    __shared__ int   rpos[NR];
    __shared__ short rid[NR];

    const int tid  = threadIdx.x;
    const int g    = tid >> 7;          // row group
    const int tx   = tid & 127;         // column-pair index
    const int lane = tid & 31;          // lane within warp
    const int xi   = 2 + 2 * tx;        // first element col of pair
    const int s    = blockIdx.x / CSZ;  // shot
    uint32_t rank;
    asm("mov.u32 %0, %%cluster_ctarank;" : "=r"(rank));
    const int r0  = (int)rank * RPC;
    const int gz0 = g * RPT;

    for (int i = tid; i < 2 * ROWS * S; i += 1024) smem[i] = 0.0f;
    // cache source wavelet: identical two-multiply rounding as reference
    if (tid < NT) sxin[tid] = (xin[s * NT + tid] * 0.001f) * 0.001f;
    if (tid == 0) {
        rcnt = 0;
        for (int i = 0; i < 4; i++) mbar_init(smem_u32(&mbars[i]), 1);
    }
    __syncthreads();
    cluster_sync_();                    // mbars initialized cluster-wide

    if (tid < NR) {
        int rz = rec_z[s * NR + tid];
        if (rz >= r0 && rz < r0 + RPC) {
            int i = atomicAdd(&rcnt, 1);
            rpos[i] = (rz - r0 + 1) * S + rec_x[s * NR + tid] + 2;
            rid[i]  = (short)tid;
        }
    }

    const int  srcz    = src_z[s];
    const int  srcx    = src_x[s];
    const int  szc     = srcz - r0;
    const bool my_src  = (szc >= gz0 && szc < gz0 + RPT) && (tx == (srcx >> 1));
    const int  szl     = szc - gz0;
    const int  srclane = srcx & 1;

    u64 c2p[RPT], ccp[RPT], nco[RPT];
#pragma unroll
    for (int z = 0; z < RPT; z++) {
        float a0 = vp[(r0 + gz0 + z) * NX + 2 * tx]     * 0.001f;
        float a1 = vp[(r0 + gz0 + z) * NX + 2 * tx + 1] * 0.001f;
        c2p[z] = f2pack((a0 * a0) * 0.01f, (a1 * a1) * 0.01f);
        ccp[z] = 0ull;
        nco[z] = 0ull;                  // -p_{t-1}
    }
    __syncthreads();                    // rcnt/rpos/rid + sxin final

    // hoist receiver bookkeeping into registers
    const bool has_rec = (tid < rcnt);
    const int  myrpos  = has_rec ? rpos[tid] : 0;
    float*     outp    = out + (size_t)s * NT * NR + (has_rec ? (int)rid[tid] : 0);

    float* const b0 = smem;
    float* const b1 = smem + ROWS * S;
    const uint32_t base0 = smem_u32(b0);
    const uint32_t base1 = smem_u32(b1);
    const uint32_t mb_top[2] = { smem_u32(&mbars[0]), smem_u32(&mbars[1]) };
    const uint32_t mb_bot[2] = { smem_u32(&mbars[2]), smem_u32(&mbars[3]) };
    const bool has_up = (rank > 0);
    const bool has_dn = (rank < CSZ - 1);
    const bool gtop   = (g == 0);
    const bool gbot   = (g == NG - 1);
    const bool lead_t = (tid == 0);              // g0 leader: top direction
    const bool lead_b = (tid == (NG - 1) * 128); // g_last leader: bottom dir

    const u64 NEG4 = f2pack(-4.0f, -4.0f);
    const u64 TWO  = f2pack( 2.0f,  2.0f);
    const u64 NEG1 = f2pack(-1.0f, -1.0f);

    const int off0  = (gz0 + 1) * S + xi;
    const int offSB = gz0 * S + xi;
    const int offSA = (gz0 + RPT + 1) * S + xi;

// one row update; horizontal halves as scalar FADDs into the result pair.
#define STEP_ROW(PN, z, below, above, oldcc, val)                              \
    {                                                                          \
        u64 cc = ccp[z];                                                       \
        float clo, chi; f2unpack(cc, clo, chi);                                \
        u64 vert = f2add(below, above);                                        \
        u64 horz = f2pack(lv[z] + chi, clo + rv[z]);                           \
        u64 lap  = f2fma(cc, NEG4, f2add(vert, horz));                         \
        u64 tmp  = f2fma(cc, TWO, nco[z]);                                     \
        val = f2fma(c2p[z], lap, tmp);                                         \
        nco[z] = f2mul(cc, NEG1);                                              \
        if (my_src && (z) == szl) {                                            \
            float a, b; f2unpack(val, a, b);                                   \
            if (srclane) b += srcval; else a += srcval;                        \
            val = f2pack(a, b);                                                \
        }                                                                      \
        ccp[z] = val;                                                          \
        f2st((PN) + off0 + (z) * S, val);                                      \
        oldcc = cc;                                                            \
    }

// One full phase, boundary-first, single full-CTA barrier.
// Horizontal neighbor exchange by warp shuffle; edge lanes fix up from the
// smem mirror (stored last step; pad columns are permanently zero).
#define DO_STEP(PCUR, PNXT, RBASE, PAR, T, WAITOK, WPAR, OUTOFF)               \
    {                                                                          \
        float srcval = 0.0f;                                                   \
        if (my_src) srcval = sxin[T];                                          \
        float lv[RPT], rv[RPT];                                                \
        _Pragma("unroll")                                                      \
        for (int z = 0; z < RPT; z++) {                                        \
            float clo, chi; f2unpack(ccp[z], clo, chi);                        \
            lv[z] = __shfl_up_sync(0xffffffffu, chi, 1);                       \
            rv[z] = __shfl_down_sync(0xffffffffu, clo, 1);                     \
        }                                                                      \
        if (lane == 0) {                                                       \
            _Pragma("unroll")                                                  \
            for (int z = 0; z < RPT; z++) lv[z] = (PCUR)[off0 + z * S - 1];    \
        }                                                                      \
        if (lane == 31) {                                                      \
            _Pragma("unroll")                                                  \
            for (int z = 0; z < RPT; z++) rv[z] = (PCUR)[off0 + z * S + 2];    \
        }                                                                      \
        u64 oldcc, val;                                                        \
        if (gtop) {                                                            \
            if (lead_t && has_up) mbar_expect(mb_top[PAR], NX * 4);            \
            const u64 seamA = f2ld((PCUR) + offSA);                            \
            const u64 save0 = ccp[0];                                          \
            const u64 save1 = ccp[1];                                          \
            if (has_up && (WAITOK)) mbar_wait(mb_top[(PAR) ^ 1], (WPAR));      \
            {   /* boundary row 0 first, push immediately */                   \
                const u64 haloB = f2ld((PCUR) + offSB);                        \
                STEP_ROW(PNXT, 0, haloB, save1, oldcc, val);                   \
                if (has_up) {                                                  \
                    uint32_t rs = mapa32((RBASE) +                             \
                        (uint32_t)((ROWS - 1) * S + xi) * 4u, rank - 1);       \
                    uint32_t rm = mapa32(mb_bot[PAR], rank - 1);               \
                    st_async_f2(rs, rm, val);                                  \
                }                                                              \
            }                                                                  \
            u64 below = save0;                                                 \
            _Pragma("unroll")                                                  \
            for (int z = 1; z < RPT; z++) {                                    \
                u64 above = (z == RPT - 1) ? seamA : ccp[z + 1];               \
                STEP_ROW(PNXT, z, below, above, oldcc, val);                   \
                below = oldcc;                                                 \
            }                                                                  \
        } else if (gbot) {                                                     \
            if (lead_b && has_dn) mbar_expect(mb_bot[PAR], NX * 4);            \
            const u64 seamB = f2ld((PCUR) + offSB);                            \
            const u64 saveL = ccp[RPT - 1];                                    \
            u64 belowB = ccp[RPT - 2];                                         \
            if (has_dn && (WAITOK)) mbar_wait(mb_bot[(PAR) ^ 1], (WPAR));      \
            {   /* boundary row RPT-1 first, push immediately */               \
                const u64 haloA = f2ld((PCUR) + offSA);                        \
                STEP_ROW(PNXT, RPT - 1, belowB, haloA, oldcc, val);            \
                if (has_dn) {                                                  \
                    uint32_t rs = mapa32((RBASE) + (uint32_t)(xi) * 4u,        \
                                         rank + 1);                            \
                    uint32_t rm = mapa32(mb_top[PAR], rank + 1);               \
                    st_async_f2(rs, rm, val);                                  \
                }                                                              \
            }                                                                  \
            u64 below = seamB;                                                 \
            _Pragma("unroll")                                                  \
            for (int z = 0; z < RPT - 1; z++) {                                \
                u64 above = (z == RPT - 2) ? saveL : ccp[z + 1];               \
                STEP_ROW(PNXT, z, below, above, oldcc, val);                   \
                below = oldcc;                                                 \
            }                                                                  \
        } else {                                                               \
            const u64 seamA = f2ld((PCUR) + offSA);                            \
            u64 below = f2ld((PCUR) + offSB);                                  \
            _Pragma("unroll")                                                  \
            for (int z = 0; z < RPT; z++) {                                    \
                u64 above = (z == RPT - 1) ? seamA : ccp[z + 1];               \
                STEP_ROW(PNXT, z, below, above, oldcc, val);                   \
                below = oldcc;                                                 \
            }                                                                  \
        }                                                                      \
        __syncthreads();                                                       \
        if (has_rec) outp[OUTOFF] = (PNXT)[myrpos];                            \
    }

    // x4 unroll: phases t mod 4 -> (PAR, WPAR) = (0,1),(1,0),(0,0),(1,1)
    for (int t = 0; t < NT; t += 4) {
        DO_STEP(b0, b1, base1, 0, t,     t > 0, 1, 0);
        DO_STEP(b1, b0, base0, 1, t + 1, true,  0, NR);
        DO_STEP(b0, b1, base1, 0, t + 2, true,  0, 2 * NR);
        DO_STEP(b1, b0, base0, 1, t + 3, true,  1, 3 * NR);
        outp += 4 * NR;
    }

    // drain final phase (NT-1 = 511: mbar[1], parity 1)
    if (lead_t && has_up) mbar_wait(mb_top[1], 1);
    if (lead_b && has_dn) mbar_wait(mb_bot[1], 1);
    __syncthreads();
    cluster_sync_();
#undef DO_STEP
#undef STEP_ROW
}

template<int CSZ>
static void launch_variant(const float* x, const float* vp, const int* sz,
                           const int* sx, const int* rz, const int* rx, float* out)
{
    const int smemb = 2 * (NZ / CSZ + 2) * S * (int)sizeof(float);
    cudaFuncSetAttribute(wave_kernel<CSZ>,
                         cudaFuncAttributeMaxDynamicSharedMemorySize, smemb);
    wave_kernel<CSZ><<<NS * CSZ, 1024, smemb>>>(x, vp, sz, sx, rz, rx, out);
}

extern "C" void kernel_launch(void* const* d_in, const int* in_sizes, int n_in,
                              void* d_out, int out_size)
{
    const float* x     = (const float*)d_in[0];
    const float* vp    = (const float*)d_in[1];
    const int*   src_z = (const int*)d_in[2];
    const int*   src_x = (const int*)d_in[3];
    const int*   rec_z = (const int*)d_in[4];
    const int*   rec_x = (const int*)d_in[5];
    float*       out   = (float*)d_out;

    const int smem16 = 2 * (NZ / 16 + 2) * S * (int)sizeof(float);
    bool use16 = false;
    if (cudaFuncSetAttribute(wave_kernel<16>,
            cudaFuncAttributeNonPortableClusterSizeAllowed, 1) == cudaSuccess &&
        cudaFuncSetAttribute(wave_kernel<16>,
            cudaFuncAttributeMaxDynamicSharedMemorySize, smem16) == cudaSuccess) {
        cudaLaunchConfig_t cfg = {};
        cfg.gridDim  = dim3(NS * 16, 1, 1);
        cfg.blockDim = dim3(1024, 1, 1);
        cfg.dynamicSmemBytes = (size_t)smem16;
        cudaLaunchAttribute attr[1];
        attr[0].id = cudaLaunchAttributeClusterDimension;
        attr[0].val.clusterDim = {16, 1, 1};
        cfg.attrs = attr;
        cfg.numAttrs = 1;
        int ncl = 0;
        if (cudaOccupancyMaxActiveClusters(&ncl, wave_kernel<16>, &cfg) == cudaSuccess
            && ncl >= NS) use16 = true;
        else cudaGetLastError();
    } else {
        cudaGetLastError();
    }

    if (use16) launch_variant<16>(x, vp, src_z, src_x, rec_z, rec_x, out);
    else       launch_variant<8>(x, vp, src_z, src_x, rec_z, rec_x, out);
}

// round 13
// speedup vs baseline: 1.1052x; 1.1052x over previous
#include <cuda_runtime.h>
#include <cstdint>

// 2D acoustic FDTD, 4 shots x 512 steps, 256x256 grid.
// NEW (R13): 8 clusters (2 per shot, z-split) x 16 CTAs x 1024 threads.
// Each CTA owns 8 rows; NG=8 row groups => RPT=1 (one row-pair per thread,
// all vertical neighbors via smem). Intra-cluster halos via st.async.b64 +
// parity mbarriers (proven). The mid-shot seam between the two clusters is
// crossed via L2 with self-synchronizing per-thread (tag,value) slots:
// release/acquire + monotonic epoch tags (graph-replay safe).
// Fallback: proven single-cluster-per-shot kernel (R11).

#define NS    4
#define NT    512
#define NZ    256
#define NX    256
#define NR    128
#define S     260          // padded row stride: cols [2..257] live, pads 0

typedef unsigned long long u64;

// ---- L2 seam state (dir 0 = upper->lower, dir 1 = lower->upper) ----
__device__ u64          gs_data[NS][2][2][128];   // [shot][dir][parity][tx]
__device__ unsigned int gs_tag [NS][2][2][128];
__device__ unsigned int g_epoch;

__device__ __forceinline__ uint32_t smem_u32(const void* p) {
    uint32_t a;
    asm("{ .reg .u64 t; cvta.to.shared.u64 t, %1; cvt.u32.u64 %0, t; }"
        : "=r"(a) : "l"(p));
    return a;
}
__device__ __forceinline__ uint32_t mapa32(uint32_t laddr, uint32_t rank) {
    uint32_t ra;
    asm("mapa.shared::cluster.u32 %0, %1, %2;" : "=r"(ra) : "r"(laddr), "r"(rank));
    return ra;
}
__device__ __forceinline__ void mbar_init(uint32_t mbar, uint32_t cnt) {
    asm volatile("mbarrier.init.shared::cta.b64 [%0], %1;" :: "r"(mbar), "r"(cnt) : "memory");
}
__device__ __forceinline__ void mbar_expect(uint32_t mbar, uint32_t tx) {
    asm volatile("mbarrier.arrive.expect_tx.shared::cta.b64 _, [%0], %1;"
                 :: "r"(mbar), "r"(tx) : "memory");
}
__device__ __forceinline__ void mbar_wait(uint32_t mbar, uint32_t parity) {
    asm volatile(
        "{\n\t"
        ".reg .pred P;\n\t"
        "LW%=:\n\t"
        "mbarrier.try_wait.parity.acquire.cluster.shared::cta.b64 P, [%0], %1;\n\t"
        "@P bra LD%=;\n\t"
        "bra LW%=;\n\t"
        "LD%=:\n\t"
        "}"
        :: "r"(mbar), "r"(parity) : "memory");
}
__device__ __forceinline__ void st_async_f2(uint32_t rslot, uint32_t rmbar, u64 v) {
    asm volatile("st.async.shared::cluster.mbarrier::complete_tx::bytes.b64 [%0], %1, [%2];"
                 :: "r"(rslot), "l"(v), "r"(rmbar) : "memory");
}
__device__ __forceinline__ void cluster_sync_() {
    asm volatile("barrier.cluster.arrive.aligned;" ::: "memory");
    asm volatile("barrier.cluster.wait.aligned;" ::: "memory");
}

// ---- global release/acquire helpers for the L2 seam ----
__device__ __forceinline__ unsigned int ld_acq_u32(const unsigned int* p) {
    unsigned int v;
    asm volatile("ld.global.acquire.gpu.b32 %0, [%1];" : "=r"(v) : "l"(p) : "memory");
    return v;
}
__device__ __forceinline__ void st_rel_u32(unsigned int* p, unsigned int v) {
    asm volatile("st.global.release.gpu.b32 [%0], %1;" :: "l"(p), "r"(v) : "memory");
}
__device__ __forceinline__ u64 ld_u64g(const u64* p) {
    u64 v;
    asm volatile("ld.global.b64 %0, [%1];" : "=l"(v) : "l"(p) : "memory");
    return v;
}
__device__ __forceinline__ void st_u64g(u64* p, u64 v) {
    asm volatile("st.global.b64 [%0], %1;" :: "l"(p), "l"(v) : "memory");
}

// ---- packed f32x2 helpers ----
__device__ __forceinline__ u64 f2pack(float lo, float hi) {
    u64 r; asm("mov.b64 %0, {%1, %2};" : "=l"(r) : "f"(lo), "f"(hi)); return r;
}
__device__ __forceinline__ void f2unpack(u64 v, float& lo, float& hi) {
    asm("mov.b64 {%0, %1}, %2;" : "=f"(lo), "=f"(hi) : "l"(v));
}
__device__ __forceinline__ u64 f2add(u64 a, u64 b) {
    u64 r; asm("add.rn.f32x2 %0, %1, %2;" : "=l"(r) : "l"(a), "l"(b)); return r;
}
__device__ __forceinline__ u64 f2mul(u64 a, u64 b) {
    u64 r; asm("mul.rn.f32x2 %0, %1, %2;" : "=l"(r) : "l"(a), "l"(b)); return r;
}
__device__ __forceinline__ u64 f2fma(u64 a, u64 b, u64 c) {
    u64 r; asm("fma.rn.f32x2 %0, %1, %2, %3;" : "=l"(r) : "l"(a), "l"(b), "l"(c)); return r;
}
__device__ __forceinline__ u64 f2ld(const float* p) {
    float2 v = *(const float2*)p; return f2pack(v.x, v.y);
}
__device__ __forceinline__ void f2st(float* p, u64 v) {
    float lo, hi; f2unpack(v, lo, hi);
    *(float2*)p = make_float2(lo, hi);
}

// ============================ NEW KERNEL (R13) ============================
#define RPC2  8
#define ROWS2 10
#define SM2F  (2 * ROWS2 * S)

__global__ void __launch_bounds__(1024, 1) __cluster_dims__(16, 1, 1)
wave_seam_kernel(const float* __restrict__ xin,
                 const float* __restrict__ vp,
                 const int*   __restrict__ src_z,
                 const int*   __restrict__ src_x,
                 const int*   __restrict__ rec_z,
                 const int*   __restrict__ rec_x,
                 float*       __restrict__ out)
{
    extern __shared__ float smem[];     // [2][ROWS2][S]
    __shared__ __align__(8) uint64_t mbars[4];
    __shared__ float sxin[NT];
    __shared__ int   rcnt;
    __shared__ int   rpos[NR];
    __shared__ short rid[NR];

    const int tid = threadIdx.x;
    const int g   = tid >> 7;           // row group 0..7 (== CTA-local row)
    const int tx  = tid & 127;
    const int xi  = 2 + 2 * tx;
    const int c   = blockIdx.x >> 4;    // cluster id 0..7
    const int s   = c >> 1;             // shot
    const int h   = c & 1;              // half: 0=upper rows, 1=lower rows
    uint32_t rank;
    asm("mov.u32 %0, %%cluster_ctarank;" : "=r"(rank));
    const int r0 = (h * 16 + (int)rank) * RPC2;

    for (int i = tid; i < SM2F; i += 1024) smem[i] = 0.0f;
    if (tid < NT) sxin[tid] = (xin[s * NT + tid] * 0.001f) * 0.001f;
    if (tid == 0) {
        rcnt = 0;
        for (int i = 0; i < 4; i++) mbar_init(smem_u32(&mbars[i]), 1);
    }
    __syncthreads();
    cluster_sync_();

    if (tid < NR) {
        int rz = rec_z[s * NR + tid];
        if (rz >= r0 && rz < r0 + RPC2) {
            int i = atomicAdd(&rcnt, 1);
            rpos[i] = (rz - r0 + 1) * S + rec_x[s * NR + tid] + 2;
            rid[i]  = (short)tid;
        }
    }

    const int  srcz    = src_z[s];
    const int  srcx    = src_x[s];
    const int  szc     = srcz - r0;
    const bool my_src  = (szc == g) && (tx == (srcx >> 1));
    const int  srclane = srcx & 1;

    u64 c2p0, ccp0 = 0ull, nco0 = 0ull;
    {
        float a0 = vp[(r0 + g) * NX + 2 * tx]     * 0.001f;
        float a1 = vp[(r0 + g) * NX + 2 * tx + 1] * 0.001f;
        c2p0 = f2pack((a0 * a0) * 0.01f, (a1 * a1) * 0.01f);
    }

    const bool has_up  = (rank > 0);
    const bool has_dn  = (rank < 15);
    const bool seam_up = (h == 1) && (rank == 0);   // consumes dir0, produces dir1
    const bool seam_dn = (h == 0) && (rank == 15);  // consumes dir1, produces dir0
    const bool gtop    = (g == 0);
    const bool gbot    = (g == 7);
    const bool lead_t  = (tid == 0);
    const bool lead_b  = (tid == 7 * 128);

    unsigned int ebase = 0;
    if ((seam_up && gtop) || (seam_dn && gbot)) {
        asm volatile("ld.global.cg.b32 %0, [%1];" : "=r"(ebase)
                     : "l"(&g_epoch) : "memory");
    }
    __syncthreads();                    // rcnt/rpos/rid + sxin final

    const bool has_rec = (tid < rcnt);
    const int  myrpos  = has_rec ? rpos[tid] : 0;
    float*     outp    = out + (size_t)s * NT * NR + (has_rec ? (int)rid[tid] : 0);

    float* const b0 = smem;
    float* const b1 = smem + ROWS2 * S;
    const uint32_t base0 = smem_u32(b0);
    const uint32_t base1 = smem_u32(b1);
    const uint32_t mb_top[2] = { smem_u32(&mbars[0]), smem_u32(&mbars[1]) };
    const uint32_t mb_bot[2] = { smem_u32(&mbars[2]), smem_u32(&mbars[3]) };

    const u64 NEG4 = f2pack(-4.0f, -4.0f);
    const u64 TWO  = f2pack( 2.0f,  2.0f);
    const u64 NEG1 = f2pack(-1.0f, -1.0f);

    const int off0 = (g + 1) * S + xi;  // smem offset of this thread's row

#define STEP_ROW1(PN, below, above, val)                                       \
    {                                                                          \
        u64 cc = ccp0;                                                         \
        float clo, chi; f2unpack(cc, clo, chi);                                \
        u64 vert = f2add(below, above);                                        \
        u64 horz = f2pack(lv + chi, clo + rv);                                 \
        u64 lap  = f2fma(cc, NEG4, f2add(vert, horz));                         \
        u64 tmp  = f2fma(cc, TWO, nco0);                                       \
        val = f2fma(c2p0, lap, tmp);                                           \
        nco0 = f2mul(cc, NEG1);                                                \
        if (my_src) {                                                          \
            float a, b; f2unpack(val, a, b);                                   \
            if (srclane) b += srcval; else a += srcval;                        \
            val = f2pack(a, b);                                                \
        }                                                                      \
        ccp0 = val;                                                            \
        f2st((PN) + off0, val);                                                \
    }

#define DO_STEP2(PCUR, PNXT, RBASE, PAR, T, WAITOK, WPAR, OUTOFF)              \
    {                                                                          \
        float srcval = 0.0f;                                                   \
        if (my_src) srcval = sxin[T];                                          \
        float2 la = *(const float2*)((PCUR) + off0 - 2);                       \
        float2 lb = *(const float2*)((PCUR) + off0 + 2);                       \
        const float lv = la.y, rv = lb.x;                                      \
        u64 below, above, val;                                                 \
        if (gtop) {                                                            \
            if (lead_t && has_up) mbar_expect(mb_top[PAR], NX * 4);            \
            above = f2ld((PCUR) + off0 + S);                                   \
            if (seam_up) {                                                     \
                if (WAITOK) {                                                  \
                    const unsigned int want = ebase + (unsigned int)(T);       \
                    const unsigned int* tp = &gs_tag[s][0][(PAR) ^ 1][tx];     \
                    while ((int)(ld_acq_u32(tp) - want) < 0) {}                \
                    below = ld_u64g(&gs_data[s][0][(PAR) ^ 1][tx]);            \
                } else below = 0ull;                                           \
            } else {                                                           \
                if (has_up && (WAITOK)) mbar_wait(mb_top[(PAR) ^ 1], (WPAR));  \
                below = f2ld((PCUR) + off0 - S);                               \
            }                                                                  \
            STEP_ROW1(PNXT, below, above, val);                                \
            if (has_up) {                                                      \
                uint32_t rs = mapa32((RBASE) +                                 \
                    (uint32_t)((ROWS2 - 1) * S + xi) * 4u, rank - 1);          \
                uint32_t rm = mapa32(mb_bot[PAR], rank - 1);                   \
                st_async_f2(rs, rm, val);                                      \
            } else if (seam_up) {                                              \
                st_u64g(&gs_data[s][1][PAR][tx], val);                         \
                st_rel_u32(&gs_tag[s][1][PAR][tx],                             \
                           ebase + (unsigned int)(T) + 1u);                    \
            }                                                                  \
        } else if (gbot) {                                                     \
            if (lead_b && has_dn) mbar_expect(mb_bot[PAR], NX * 4);            \
            below = f2ld((PCUR) + off0 - S);                                   \
            if (seam_dn) {                                                     \
                if (WAITOK) {                                                  \
                    const unsigned int want = ebase + (unsigned int)(T);       \
                    const unsigned int* tp = &gs_tag[s][1][(PAR) ^ 1][tx];     \
                    while ((int)(ld_acq_u32(tp) - want) < 0) {}                \
                    above = ld_u64g(&gs_data[s][1][(PAR) ^ 1][tx]);            \
                } else above = 0ull;                                           \
            } else {                                                           \
                if (has_dn && (WAITOK)) mbar_wait(mb_bot[(PAR) ^ 1], (WPAR));  \
                above = f2ld((PCUR) + off0 + S);                               \
            }                                                                  \
            STEP_ROW1(PNXT, below, above, val);                                \
            if (has_dn) {                                                      \
                uint32_t rs = mapa32((RBASE) + (uint32_t)(xi) * 4u, rank + 1); \
                uint32_t rm = mapa32(mb_top[PAR], rank + 1);                   \
                st_async_f2(rs, rm, val);                                      \
            } else if (seam_dn) {                                              \
                st_u64g(&gs_data[s][0][PAR][tx], val);                         \
                st_rel_u32(&gs_tag[s][0][PAR][tx],                             \
                           ebase + (unsigned int)(T) + 1u);                    \
            }                                                                  \
        } else {                                                               \
            below = f2ld((PCUR) + off0 - S);                                   \
            above = f2ld((PCUR) + off0 + S);                                   \
            STEP_ROW1(PNXT, below, above, val);                                \
        }                                                                      \
        __syncthreads();                                                       \
        if (has_rec) outp[OUTOFF] = (PNXT)[myrpos];                            \
    }

    // x4 unroll: phases t mod 4 -> (PAR, WPAR) = (0,1),(1,0),(0,0),(1,1)
    for (int t = 0; t < NT; t += 4) {
        DO_STEP2(b0, b1, base1, 0, t,     t > 0, 1, 0);
        DO_STEP2(b1, b0, base0, 1, t + 1, true,  0, NR);
        DO_STEP2(b0, b1, base1, 0, t + 2, true,  0, 2 * NR);
        DO_STEP2(b1, b0, base0, 1, t + 3, true,  1, 3 * NR);
        outp += 4 * NR;
    }

    // drain final DSMEM phase (NT-1 = 511: mbar[1], parity 1)
    if (lead_t && has_up) mbar_wait(mb_top[1], 1);
    if (lead_b && has_dn) mbar_wait(mb_bot[1], 1);
    __syncthreads();
    cluster_sync_();

    // advance epoch once per launch (stream order protects next launch)
    if (blockIdx.x == 0 && tid == 0) atomicAdd(&g_epoch, (unsigned int)NT);
#undef DO_STEP2
#undef STEP_ROW1
}

// ========================= FALLBACK KERNEL (R11) ==========================
#define NG    8

template<int CSZ>
__global__ void __launch_bounds__(1024, 1) __cluster_dims__(CSZ, 1, 1)
wave_kernel_fb(const float* __restrict__ xin,
               const float* __restrict__ vp,
               const int*   __restrict__ src_z,
               const int*   __restrict__ src_x,
               const int*   __restrict__ rec_z,
               const int*   __restrict__ rec_x,
               float*       __restrict__ out)
{
    constexpr int RPC  = NZ / CSZ;
    constexpr int RPT  = RPC / NG;
    constexpr int ROWS = RPC + 2;
    extern __shared__ float smem[];
    __shared__ __align__(8) uint64_t mbars[4];
    __shared__ float sxin[NT];
    __shared__ int   rcnt;
    __shared__ int   rpos[NR];
    __shared__ short rid[NR];

    const int tid = threadIdx.x;
    const int g   = tid >> 7;
    const int tx  = tid & 127;
    const int xi  = 2 + 2 * tx;
    const int s   = blockIdx.x / CSZ;
    uint32_t rank;
    asm("mov.u32 %0, %%cluster_ctarank;" : "=r"(rank));
    const int r0  = (int)rank * RPC;
    const int gz0 = g * RPT;

    for (int i = tid; i < 2 * ROWS * S; i += 1024) smem[i] = 0.0f;
    if (tid < NT) sxin[tid] = (xin[s * NT + tid] * 0.001f) * 0.001f;
    if (tid == 0) {
        rcnt = 0;
        for (int i = 0; i < 4; i++) mbar_init(smem_u32(&mbars[i]), 1);
    }
    __syncthreads();
    cluster_sync_();

    if (tid < NR) {
        int rz = rec_z[s * NR + tid];
        if (rz >= r0 && rz < r0 + RPC) {
            int i = atomicAdd(&rcnt, 1);
            rpos[i] = (rz - r0 + 1) * S + rec_x[s * NR + tid] + 2;
            rid[i]  = (short)tid;
        }
    }

    const int  srcz    = src_z[s];
    const int  srcx    = src_x[s];
    const int  szc     = srcz - r0;
    const bool my_src  = (szc >= gz0 && szc < gz0 + RPT) && (tx == (srcx >> 1));
    const int  szl     = szc - gz0;
    const int  srclane = srcx & 1;

    u64 c2p[RPT], ccp[RPT], nco[RPT];
#pragma unroll
    for (int z = 0; z < RPT; z++) {
        float a0 = vp[(r0 + gz0 + z) * NX + 2 * tx]     * 0.001f;
        float a1 = vp[(r0 + gz0 + z) * NX + 2 * tx + 1] * 0.001f;
        c2p[z] = f2pack((a0 * a0) * 0.01f, (a1 * a1) * 0.01f);
        ccp[z] = 0ull;
        nco[z] = 0ull;
    }
    __syncthreads();

    const bool has_rec = (tid < rcnt);
    const int  myrpos  = has_rec ? rpos[tid] : 0;
    float*     outp    = out + (size_t)s * NT * NR + (has_rec ? (int)rid[tid] : 0);

    float* const b0 = smem;
    float* const b1 = smem + ROWS * S;
    const uint32_t base0 = smem_u32(b0);
    const uint32_t base1 = smem_u32(b1);
    const uint32_t mb_top[2] = { smem_u32(&mbars[0]), smem_u32(&mbars[1]) };
    const uint32_t mb_bot[2] = { smem_u32(&mbars[2]), smem_u32(&mbars[3]) };
    const bool has_up = (rank > 0);
    const bool has_dn = (rank < CSZ - 1);
    const bool gtop   = (g == 0);
    const bool gbot   = (g == NG - 1);
    const bool lead_t = (tid == 0);
    const bool lead_b = (tid == (NG - 1) * 128);

    const u64 NEG4 = f2pack(-4.0f, -4.0f);
    const u64 TWO  = f2pack( 2.0f,  2.0f);
    const u64 NEG1 = f2pack(-1.0f, -1.0f);

    const int off0  = (gz0 + 1) * S + xi;
    const int offSB = gz0 * S + xi;
    const int offSA = (gz0 + RPT + 1) * S + xi;

#define STEP_ROW(PN, z, below, above, oldcc, val)                              \
    {                                                                          \
        u64 cc = ccp[z];                                                       \
        float clo, chi; f2unpack(cc, clo, chi);                                \
        u64 vert = f2add(below, above);                                        \
        u64 horz = f2pack(lv[z] + chi, clo + rv[z]);                           \
        u64 lap  = f2fma(cc, NEG4, f2add(vert, horz));                         \
        u64 tmp  = f2fma(cc, TWO, nco[z]);                                     \
        val = f2fma(c2p[z], lap, tmp);                                         \
        nco[z] = f2mul(cc, NEG1);                                              \
        if (my_src && (z) == szl) {                                            \
            float a, b; f2unpack(val, a, b);                                   \
            if (srclane) b += srcval; else a += srcval;                        \
            val = f2pack(a, b);                                                \
        }                                                                      \
        ccp[z] = val;                                                          \
        f2st((PN) + off0 + (z) * S, val);                                      \
        oldcc = cc;                                                            \
    }

#define DO_STEP(PCUR, PNXT, RBASE, PAR, T, WAITOK, WPAR, OUTOFF)               \
    {                                                                          \
        float srcval = 0.0f;                                                   \
        if (my_src) srcval = sxin[T];                                          \
        float lv[RPT], rv[RPT];                                                \
        _Pragma("unroll")                                                      \
        for (int z = 0; z < RPT; z++) {                                        \
            float2 a = *(const float2*)((PCUR) + off0 + z * S - 2);            \
            float2 b = *(const float2*)((PCUR) + off0 + z * S + 2);            \
            lv[z] = a.y; rv[z] = b.x;                                          \
        }                                                                      \
        u64 oldcc, val;                                                        \
        if (gtop) {                                                            \
            if (lead_t && has_up) mbar_expect(mb_top[PAR], NX * 4);            \
            const u64 seamA = f2ld((PCUR) + offSA);                            \
            const u64 save0 = ccp[0];                                          \
            const u64 save1 = ccp[1];                                          \
            if (has_up && (WAITOK)) mbar_wait(mb_top[(PAR) ^ 1], (WPAR));      \
            {                                                                  \
                const u64 haloB = f2ld((PCUR) + offSB);                        \
                STEP_ROW(PNXT, 0, haloB, save1, oldcc, val);                   \
                if (has_up) {                                                  \
                    uint32_t rs = mapa32((RBASE) +                             \
                        (uint32_t)((ROWS - 1) * S + xi) * 4u, rank - 1);       \
                    uint32_t rm = mapa32(mb_bot[PAR], rank - 1);               \
                    st_async_f2(rs, rm, val);                                  \
                }                                                              \
            }                                                                  \
            u64 below = save0;                                                 \
            _Pragma("unroll")                                                  \
            for (int z = 1; z < RPT; z++) {                                    \
                u64 above = (z == RPT - 1) ? seamA : ccp[z + 1];               \
                STEP_ROW(PNXT, z, below, above, oldcc, val);                   \
                below = oldcc;                                                 \
            }                                                                  \
        } else if (gbot) {                                                     \
            if (lead_b && has_dn) mbar_expect(mb_bot[PAR], NX * 4);            \
            const u64 seamB = f2ld((PCUR) + offSB);                            \
            const u64 saveL = ccp[RPT - 1];                                    \
            u64 belowB = ccp[RPT - 2];                                         \
            if (has_dn && (WAITOK)) mbar_wait(mb_bot[(PAR) ^ 1], (WPAR));      \
            {                                                                  \
                const u64 haloA = f2ld((PCUR) + offSA);                        \
                STEP_ROW(PNXT, RPT - 1, belowB, haloA, oldcc, val);            \
                if (has_dn) {                                                  \
                    uint32_t rs = mapa32((RBASE) + (uint32_t)(xi) * 4u,        \
                                         rank + 1);                            \
                    uint32_t rm = mapa32(mb_top[PAR], rank + 1);               \
                    st_async_f2(rs, rm, val);                                  \
                }                                                              \
            }                                                                  \
            u64 below = seamB;                                                 \
            _Pragma("unroll")                                                  \
            for (int z = 0; z < RPT - 1; z++) {                                \
                u64 above = (z == RPT - 2) ? saveL : ccp[z + 1];               \
                STEP_ROW(PNXT, z, below, above, oldcc, val);                   \
                below = oldcc;                                                 \
            }                                                                  \
        } else {                                                               \
            const u64 seamA = f2ld((PCUR) + offSA);                            \
            u64 below = f2ld((PCUR) + offSB);                                  \
            _Pragma("unroll")                                                  \
            for (int z = 0; z < RPT; z++) {                                    \
                u64 above = (z == RPT - 1) ? seamA : ccp[z + 1];               \
                STEP_ROW(PNXT, z, below, above, oldcc, val);                   \
                below = oldcc;                                                 \
            }                                                                  \
        }                                                                      \
        __syncthreads();                                                       \
        if (has_rec) outp[OUTOFF] = (PNXT)[myrpos];                            \
    }

    for (int t = 0; t < NT; t += 4) {
        DO_STEP(b0, b1, base1, 0, t,     t > 0, 1, 0);
        DO_STEP(b1, b0, base0, 1, t + 1, true,  0, NR);
        DO_STEP(b0, b1, base1, 0, t + 2, true,  0, 2 * NR);
        DO_STEP(b1, b0, base0, 1, t + 3, true,  1, 3 * NR);
        outp += 4 * NR;
    }

    if (lead_t && has_up) mbar_wait(mb_top[1], 1);
    if (lead_b && has_dn) mbar_wait(mb_bot[1], 1);
    __syncthreads();
    cluster_sync_();
#undef DO_STEP
#undef STEP_ROW
}

// ============================== LAUNCHER ==================================
extern "C" void kernel_launch(void* const* d_in, const int* in_sizes, int n_in,
                              void* d_out, int out_size)
{
    const float* x     = (const float*)d_in[0];
    const float* vp    = (const float*)d_in[1];
    const int*   src_z = (const int*)d_in[2];
    const int*   src_x = (const int*)d_in[3];
    const int*   rec_z = (const int*)d_in[4];
    const int*   rec_x = (const int*)d_in[5];
    float*       out   = (float*)d_out;

    const int smemNew = SM2F * (int)sizeof(float);

    // ---- try new 8-cluster kernel ----
    bool useNew = false;
    if (cudaFuncSetAttribute(wave_seam_kernel,
            cudaFuncAttributeNonPortableClusterSizeAllowed, 1) == cudaSuccess &&
        cudaFuncSetAttribute(wave_seam_kernel,
            cudaFuncAttributeMaxDynamicSharedMemorySize, smemNew) == cudaSuccess) {
        cudaLaunchConfig_t cfg = {};
        cfg.gridDim  = dim3(8 * 16, 1, 1);
        cfg.blockDim = dim3(1024, 1, 1);
        cfg.dynamicSmemBytes = (size_t)smemNew;
        cudaLaunchAttribute attr[1];
        attr[0].id = cudaLaunchAttributeClusterDimension;
        attr[0].val.clusterDim = {16, 1, 1};
        cfg.attrs = attr;
        cfg.numAttrs = 1;
        int ncl = 0;
        if (cudaOccupancyMaxActiveClusters(&ncl, wave_seam_kernel, &cfg) == cudaSuccess
            && ncl >= 8) useNew = true;
        else cudaGetLastError();
    } else {
        cudaGetLastError();
    }

    if (useNew) {
        wave_seam_kernel<<<8 * 16, 1024, smemNew>>>(
            x, vp, src_z, src_x, rec_z, rec_x, out);
        return;
    }

    // ---- fallback: proven single-cluster-per-shot kernel ----
    const int smem16 = 2 * (NZ / 16 + 2) * S * (int)sizeof(float);
    bool use16 = false;
    if (cudaFuncSetAttribute(wave_kernel_fb<16>,
            cudaFuncAttributeNonPortableClusterSizeAllowed, 1) == cudaSuccess &&
        cudaFuncSetAttribute(wave_kernel_fb<16>,
            cudaFuncAttributeMaxDynamicSharedMemorySize, smem16) == cudaSuccess) {
        cudaLaunchConfig_t cfg = {};
        cfg.gridDim  = dim3(NS * 16, 1, 1);
        cfg.blockDim = dim3(1024, 1, 1);
        cfg.dynamicSmemBytes = (size_t)smem16;
        cudaLaunchAttribute attr[1];
        attr[0].id = cudaLaunchAttributeClusterDimension;
        attr[0].val.clusterDim = {16, 1, 1};
        cfg.attrs = attr;
        cfg.numAttrs = 1;
        int ncl = 0;
        if (cudaOccupancyMaxActiveClusters(&ncl, wave_kernel_fb<16>, &cfg) == cudaSuccess
            && ncl >= NS) use16 = true;
        else cudaGetLastError();
    } else {
        cudaGetLastError();
    }

    if (use16) {
        wave_kernel_fb<16><<<NS * 16, 1024, smem16>>>(
            x, vp, src_z, src_x, rec_z, rec_x, out);
    } else {
        const int smem8 = 2 * (NZ / 8 + 2) * S * (int)sizeof(float);
        cudaFuncSetAttribute(wave_kernel_fb<8>,
            cudaFuncAttributeMaxDynamicSharedMemorySize, smem8);
        wave_kernel_fb<8><<<NS * 8, 1024, smem8>>>(
            x, vp, src_z, src_x, rec_z, rec_x, out);
    }
}